// round 4
// baseline (speedup 1.0000x reference)
#include <cuda_runtime.h>
#include <cstdint>
#include <cstddef>

#define N_ALL 8192
#define N_SUP 2048
#define N_QRY 6144
#define D_IN  512
#define D_MOD 256
#define NCLS  64
#define KNN   10
#define NW    (N_ALL/32)   // 256 words per bitset row

// ---- scratch (device globals; no allocation APIs) ----
__device__ float    g_emb[N_ALL * D_MOD];            // 8 MB
__device__ float    g_sq[N_ALL];
__device__ float    g_dist[(size_t)N_ALL * N_ALL];   // 256 MB
__device__ int      g_topk[N_ALL * KNN];
__device__ unsigned g_adj[N_ALL * NW];               // 8 MB bitset
__device__ float    g_deg[N_ALL];
__device__ float    g_lab0[N_ALL * NCLS];
__device__ float    g_lab1[N_ALL * NCLS];

// ============================================================
// 1) Embedding GEMM: [8192 x 512] @ [512 x 256] -> g_emb
//    128x128 block tile, 8x8 per thread, BK=16, 256 threads.
// ============================================================
__global__ void embed_gemm(const float* __restrict__ sup,
                           const float* __restrict__ qry,
                           const float* __restrict__ W) {
    __shared__ float As[16][128];
    __shared__ float Bs[16][128];
    const int bn = blockIdx.x, bm = blockIdx.y;
    const int tid = threadIdx.x;
    const int tx = tid & 15, ty = tid >> 4;
    float acc[8][8];
    #pragma unroll
    for (int i = 0; i < 8; i++)
        #pragma unroll
        for (int j = 0; j < 8; j++) acc[i][j] = 0.f;

    for (int k0 = 0; k0 < D_IN; k0 += 16) {
        // A tile (transposed into As[k][m])
        #pragma unroll
        for (int p = 0; p < 2; p++) {
            int m  = p * 64 + (tid >> 2);
            int c4 = tid & 3;
            int row = bm * 128 + m;
            const float* Ar = (row < N_SUP) ? (sup + (size_t)row * D_IN)
                                            : (qry + (size_t)(row - N_SUP) * D_IN);
            float4 v = *(const float4*)(Ar + k0 + c4 * 4);
            As[c4*4+0][m] = v.x; As[c4*4+1][m] = v.y;
            As[c4*4+2][m] = v.z; As[c4*4+3][m] = v.w;
        }
        // B tile (natural layout)
        #pragma unroll
        for (int p = 0; p < 2; p++) {
            int r = p * 8 + (tid >> 5);
            int c = (tid & 31) * 4;
            float4 v = *(const float4*)(W + (size_t)(k0 + r) * D_MOD + bn * 128 + c);
            *(float4*)&Bs[r][c] = v;
        }
        __syncthreads();
        #pragma unroll
        for (int k = 0; k < 16; k++) {
            float a[8], b[8];
            *(float4*)&a[0] = *(float4*)&As[k][ty*8];
            *(float4*)&a[4] = *(float4*)&As[k][ty*8+4];
            *(float4*)&b[0] = *(float4*)&Bs[k][tx*8];
            *(float4*)&b[4] = *(float4*)&Bs[k][tx*8+4];
            #pragma unroll
            for (int i = 0; i < 8; i++)
                #pragma unroll
                for (int j = 0; j < 8; j++)
                    acc[i][j] = fmaf(a[i], b[j], acc[i][j]);
        }
        __syncthreads();
    }
    #pragma unroll
    for (int i = 0; i < 8; i++) {
        int row = bm * 128 + ty * 8 + i;
        #pragma unroll
        for (int j = 0; j < 8; j += 4) {
            int col = bn * 128 + tx * 8 + j;
            *(float4*)&g_emb[(size_t)row * D_MOD + col] =
                make_float4(acc[i][j], acc[i][j+1], acc[i][j+2], acc[i][j+3]);
        }
    }
}

// ============================================================
// 2) Squared norms (one warp per row)
// ============================================================
__global__ void sqnorm_kernel() {
    int row  = blockIdx.x * 8 + (threadIdx.x >> 5);
    int lane = threadIdx.x & 31;
    float s = 0.f;
    #pragma unroll
    for (int c = lane; c < D_MOD; c += 32) {
        float v = g_emb[(size_t)row * D_MOD + c];
        s = fmaf(v, v, s);
    }
    #pragma unroll
    for (int o = 16; o; o >>= 1) s += __shfl_xor_sync(~0u, s, o);
    if (!lane) g_sq[row] = s;
}

// ============================================================
// 3) Distance matrix: dist[i][j] = sqrt(max(sq_i + sq_j - 2*dot, 0))
//    Same 128x128 SGEMM structure; both operands are g_emb rows.
// ============================================================
__global__ void dist_gemm() {
    __shared__ float As[16][128];
    __shared__ float Bs[16][128];
    const int bn = blockIdx.x, bm = blockIdx.y;
    const int tid = threadIdx.x;
    const int tx = tid & 15, ty = tid >> 4;
    float acc[8][8];
    #pragma unroll
    for (int i = 0; i < 8; i++)
        #pragma unroll
        for (int j = 0; j < 8; j++) acc[i][j] = 0.f;

    for (int k0 = 0; k0 < D_MOD; k0 += 16) {
        #pragma unroll
        for (int p = 0; p < 2; p++) {
            int m  = p * 64 + (tid >> 2);
            int c4 = tid & 3;
            float4 va = *(const float4*)&g_emb[(size_t)(bm*128 + m) * D_MOD + k0 + c4*4];
            As[c4*4+0][m] = va.x; As[c4*4+1][m] = va.y;
            As[c4*4+2][m] = va.z; As[c4*4+3][m] = va.w;
            float4 vb = *(const float4*)&g_emb[(size_t)(bn*128 + m) * D_MOD + k0 + c4*4];
            Bs[c4*4+0][m] = vb.x; Bs[c4*4+1][m] = vb.y;
            Bs[c4*4+2][m] = vb.z; Bs[c4*4+3][m] = vb.w;
        }
        __syncthreads();
        #pragma unroll
        for (int k = 0; k < 16; k++) {
            float a[8], b[8];
            *(float4*)&a[0] = *(float4*)&As[k][ty*8];
            *(float4*)&a[4] = *(float4*)&As[k][ty*8+4];
            *(float4*)&b[0] = *(float4*)&Bs[k][tx*8];
            *(float4*)&b[4] = *(float4*)&Bs[k][tx*8+4];
            #pragma unroll
            for (int i = 0; i < 8; i++)
                #pragma unroll
                for (int j = 0; j < 8; j++)
                    acc[i][j] = fmaf(a[i], b[j], acc[i][j]);
        }
        __syncthreads();
    }
    const int ibase = bm * 128 + ty * 8;
    const int jbase = bn * 128 + tx * 8;
    float sqi[8], sqj[8];
    #pragma unroll
    for (int i = 0; i < 8; i++) sqi[i] = g_sq[ibase + i];
    #pragma unroll
    for (int j = 0; j < 8; j++) sqj[j] = g_sq[jbase + j];
    #pragma unroll
    for (int i = 0; i < 8; i++) {
        float o[8];
        #pragma unroll
        for (int j = 0; j < 8; j++) {
            float d2 = sqi[i] + sqj[j] - 2.0f * acc[i][j];
            o[j] = sqrtf(fmaxf(d2, 0.f));
        }
        size_t off = (size_t)(ibase + i) * N_ALL + jbase;
        *(float4*)&g_dist[off]     = make_float4(o[0], o[1], o[2], o[3]);
        *(float4*)&g_dist[off + 4] = make_float4(o[4], o[5], o[6], o[7]);
    }
}

// ============================================================
// 4) Top-K per row, exact jax.lax.top_k tie semantics:
//    ascending dist, ties -> smaller index.
//    Key = (dist_bits << 32) | idx  (dist >= 0 so bit order == value order)
// ============================================================
__global__ void topk_kernel() {
    const int row = blockIdx.x;
    const int tid = threadIdx.x;           // 256 threads
    const float* __restrict__ dr = &g_dist[(size_t)row * N_ALL];

    unsigned long long loc[KNN];
    #pragma unroll
    for (int i = 0; i < KNN; i++) loc[i] = ~0ull;

    for (int j = tid; j < N_ALL; j += 256) {
        unsigned db = __float_as_uint(dr[j]);
        unsigned long long key = ((unsigned long long)db << 32) | (unsigned)j;
        if (key < loc[KNN-1]) {
            int p = KNN - 1;
            #pragma unroll
            for (int q = KNN - 1; q > 0; q--) {
                if (loc[q-1] > key) { loc[q] = loc[q-1]; p = q - 1; }
                else break;
            }
            loc[p] = key;
        }
    }

    __shared__ unsigned long long wmin[8];
    __shared__ unsigned long long gmin;
    unsigned long long h = loc[0];
    int hp = 1;
    for (int sel = 0; sel < KNN; sel++) {
        unsigned long long v = h;
        #pragma unroll
        for (int o = 16; o; o >>= 1) {
            unsigned long long u = __shfl_xor_sync(~0u, v, o);
            if (u < v) v = u;
        }
        if ((tid & 31) == 0) wmin[tid >> 5] = v;
        __syncthreads();
        if (tid == 0) {
            unsigned long long m = wmin[0];
            #pragma unroll
            for (int i = 1; i < 8; i++) if (wmin[i] < m) m = wmin[i];
            gmin = m;
            g_topk[row * KNN + sel] = (int)(m & 0xffffffffu);
        }
        __syncthreads();
        unsigned long long m = gmin;
        if (h == m) { h = (hp < KNN) ? loc[hp] : ~0ull; hp++; }
        __syncthreads();
    }
}

// ============================================================
// 5) Adjacency bitset (symmetrized), degree
// ============================================================
__global__ void zero_adj() {
    int i = blockIdx.x * 256 + threadIdx.x;
    g_adj[i] = 0u;
}
__global__ void build_adj() {
    int e = blockIdx.x * 256 + threadIdx.x;
    if (e >= N_ALL * KNN) return;
    int i = e / KNN;
    int j = g_topk[e];
    atomicOr(&g_adj[(size_t)i * NW + (j >> 5)], 1u << (j & 31));
    atomicOr(&g_adj[(size_t)j * NW + (i >> 5)], 1u << (i & 31));
}
__global__ void degree_kernel() {
    int row  = blockIdx.x * 8 + (threadIdx.x >> 5);
    int lane = threadIdx.x & 31;
    int c = 0;
    #pragma unroll
    for (int w = lane; w < NW; w += 32) c += __popc(g_adj[(size_t)row * NW + w]);
    #pragma unroll
    for (int o = 16; o; o >>= 1) c += __shfl_xor_sync(~0u, c, o);
    if (!lane) g_deg[row] = (float)c;
}

// ============================================================
// 6) Label propagation (3 iterations). trans = adj/deg (row).
// ============================================================
__global__ void init_labels(const int* __restrict__ slab) {
    int i = blockIdx.x * 256 + threadIdx.x;   // 8192*64 / 256 blocks
    int row = i >> 6, c = i & 63;
    g_lab0[i] = (row < N_SUP && slab[row] == c) ? 1.f : 0.f;
}
__global__ void propagate(int iter) {
    const float* __restrict__ lin  = (iter & 1) ? g_lab1 : g_lab0;
    float* __restrict__       lout = (iter & 1) ? g_lab0 : g_lab1;
    const int row = blockIdx.x;
    const int c   = threadIdx.x;   // 64 threads = 64 classes
    __shared__ unsigned w[NW];
    for (int k = c; k < NW; k += 64) w[k] = g_adj[(size_t)row * NW + k];
    __syncthreads();
    const float t = 1.0f / g_deg[row];
    float acc = 0.f;
    for (int k = 0; k < NW; k++) {
        unsigned m = w[k];
        while (m) {
            int b = __ffs(m) - 1;
            m &= m - 1;
            int j = (k << 5) | b;
            acc = fmaf(t, lin[(size_t)j * NCLS + c], acc);
        }
    }
    lout[(size_t)row * NCLS + c] = acc;
}

// ============================================================
// 7) Argmax (first-max tie-break) + one-hot output for query rows
// ============================================================
__global__ void out_kernel(float* __restrict__ out) {
    int r    = blockIdx.x * 4 + (threadIdx.x >> 5);   // 6144 rows
    int lane = threadIdx.x & 31;
    const float* L = &g_lab1[(size_t)(r + N_SUP) * NCLS];
    float v0 = L[lane], v1 = L[lane + 32];
    float bv; int bi;
    if (v1 > v0) { bv = v1; bi = lane + 32; } else { bv = v0; bi = lane; }
    #pragma unroll
    for (int o = 16; o; o >>= 1) {
        float ov = __shfl_xor_sync(~0u, bv, o);
        int   oi = __shfl_xor_sync(~0u, bi, o);
        if (ov > bv || (ov == bv && oi < bi)) { bv = ov; bi = oi; }
    }
    out[(size_t)r * NCLS + lane]      = (lane == bi)      ? 1.f : 0.f;
    out[(size_t)r * NCLS + 32 + lane] = (lane + 32 == bi) ? 1.f : 0.f;
}

// ============================================================
// launch
// ============================================================
extern "C" void kernel_launch(void* const* d_in, const int* in_sizes, int n_in,
                              void* d_out, int out_size) {
    const float* sup  = (const float*)d_in[0];   // (1, 2048, 512)
    const float* qry  = (const float*)d_in[1];   // (1, 6144, 512)
    const int*   slab = (const int*)d_in[2];     // (2048,)
    const float* W    = (const float*)d_in[3];   // (512, 256)
    float* out        = (float*)d_out;           // (1, 6144, 64)

    embed_gemm<<<dim3(D_MOD / 128, N_ALL / 128), 256>>>(sup, qry, W);
    sqnorm_kernel<<<N_ALL / 8, 256>>>();
    dist_gemm<<<dim3(N_ALL / 128, N_ALL / 128), 256>>>();
    topk_kernel<<<N_ALL, 256>>>();
    zero_adj<<<(N_ALL * NW) / 256, 256>>>();
    build_adj<<<(N_ALL * KNN + 255) / 256, 256>>>();
    degree_kernel<<<N_ALL / 8, 256>>>();
    init_labels<<<(N_ALL * NCLS) / 256, 256>>>(slab);
    propagate<<<N_ALL, 64>>>(0);   // lab0 -> lab1
    propagate<<<N_ALL, 64>>>(1);   // lab1 -> lab0
    propagate<<<N_ALL, 64>>>(0);   // lab0 -> lab1
    out_kernel<<<N_QRY / 4, 128>>>(out);
}